// round 7
// baseline (speedup 1.0000x reference)
#include <cuda_runtime.h>
#include <cuda_bf16.h>
#include <cfloat>
#include <cstdint>

#define B_ROWS 4096
#define KDIM   256
#define MEM    65536
#define VDIM   8
#define SPARS  32
#define TPB    256
#define TPB1   128
#define BM     128
#define BN     128
#define KC     64
#define SPLITS 32
#define COLS_SPLIT (MEM/SPLITS)   // 2048
#define NTILES (COLS_SPLIT/BN)    // 16
#define NCHK   (KDIM/KC)          // 4
#define TOTCHK (NTILES*NCHK)      // 64
#define CAP    512
#define ZTH    2.95f

// smem: 2 stages x (A chunk + B chunk), chunk = 128 rows x 72 bf16
#define ASTR    72
#define CHUNK_B (BM*ASTR*2)        // 18432
#define BUF_B   (2*CHUNK_B)        // 36864
#define SM_THR  (2*BUF_B)          // 73728
#define SMEM_TOTAL (SM_THR + BM*4) // 74240 -> 2 CTAs/SM

// ---- device scratch ----
__device__ __align__(16) __nv_bfloat16 g_kb[B_ROWS*KDIM];
__device__ __align__(16) __nv_bfloat16 g_pb[MEM*KDIM];
__device__ float g_thr[B_ROWS];
__device__ int   g_cnt[B_ROWS];
__device__ int   g_cand[B_ROWS*CAP];
__device__ int   g_topk[B_ROWS*SPARS];
__device__ float g_delta[B_ROWS*VDIM];

__device__ __forceinline__ uint32_t smem_u32(const void* p){
    uint32_t a;
    asm("{ .reg .u64 t; cvta.to.shared.u64 t, %1; cvt.u32.u64 %0, t; }" : "=r"(a) : "l"(p));
    return a;
}
__device__ __forceinline__ void cpasync16(uint32_t dst, const void* src){
    asm volatile("cp.async.cg.shared.global [%0], [%1], 16;" :: "r"(dst), "l"(src));
}
__device__ __forceinline__ void ldsm4(uint32_t &r0, uint32_t &r1, uint32_t &r2, uint32_t &r3,
                                      uint32_t addr){
    asm volatile("ldmatrix.sync.aligned.m8n8.x4.shared.b16 {%0,%1,%2,%3}, [%4];"
                 : "=r"(r0), "=r"(r1), "=r"(r2), "=r"(r3) : "r"(addr));
}
__device__ __forceinline__ void mma16816(float* c,
                                         const uint32_t* a,
                                         uint32_t b0, uint32_t b1){
    asm volatile(
        "mma.sync.aligned.m16n8k16.row.col.f32.bf16.bf16.f32 "
        "{%0,%1,%2,%3}, {%4,%5,%6,%7}, {%8,%9}, {%0,%1,%2,%3};"
        : "+f"(c[0]), "+f"(c[1]), "+f"(c[2]), "+f"(c[3])
        : "r"(a[0]), "r"(a[1]), "r"(a[2]), "r"(a[3]), "r"(b0), "r"(b1));
}

// ============================================================
// K0a: fp32 -> bf16
// ============================================================
#define NK4 (B_ROWS*KDIM/4)
#define NP4 (MEM*KDIM/4)
__global__ void k_cvt(const float* __restrict__ keys, const float* __restrict__ proj){
    int gid = blockIdx.x*blockDim.x + threadIdx.x;
    if(gid < NK4){
        float4 v = ((const float4*)keys)[gid];
        __nv_bfloat162 lo = __floats2bfloat162_rn(v.x, v.y);
        __nv_bfloat162 hi = __floats2bfloat162_rn(v.z, v.w);
        ((uint2*)g_kb)[gid] = make_uint2(*(uint32_t*)&lo, *(uint32_t*)&hi);
    } else {
        int j = gid - NK4;
        float4 v = ((const float4*)proj)[j];
        __nv_bfloat162 lo = __floats2bfloat162_rn(v.x, v.y);
        __nv_bfloat162 hi = __floats2bfloat162_rn(v.z, v.w);
        ((uint2*)g_pb)[j] = make_uint2(*(uint32_t*)&lo, *(uint32_t*)&hi);
    }
}

// ============================================================
// K0b: per-row threshold + zero counters
// ============================================================
__global__ void k_thr(const float* __restrict__ keys){
    int gt = blockIdx.x*blockDim.x + threadIdx.x;
    int gw = gt >> 5, lane = gt & 31;
    if(gw >= B_ROWS) return;
    float s = 0.f;
    #pragma unroll
    for(int i=0;i<KDIM/32;i++){
        float v = keys[(size_t)gw*KDIM + i*32 + lane];
        s += v*v;
    }
    #pragma unroll
    for(int off=16; off; off>>=1) s += __shfl_xor_sync(0xffffffffu, s, off);
    if(lane == 0){
        g_thr[gw] = ZTH * sqrtf(s) * (1.0f/16.0f);
        g_cnt[gw] = 0;
    }
}

// ============================================================
// K1: bf16 mma.sync GEMM, 64x64 warp tiles, frag double-buffer
// grid (32, 32), block 128, 2 CTAs/SM
// ============================================================
__global__ __launch_bounds__(TPB1,2)
void k_scores(){
    extern __shared__ char sm[];
    float* s_thr = (float*)(sm + SM_THR);
    const uint32_t smb = smem_u32(sm);

    const int tid  = threadIdx.x;
    const int lane = tid & 31;
    const int w    = tid >> 5;       // 0..3
    const int wm   = w >> 1;         // 0..1
    const int wn   = w & 1;          // 0..1
    const int row0 = blockIdx.x * BM;
    const int col0 = blockIdx.y * COLS_SPLIT;

    s_thr[tid] = g_thr[row0 + tid];

    const uint32_t a_off = (uint32_t)((wm*64 + (lane&15))*ASTR + (lane>>4)*8)*2;
    const uint32_t b_off = (uint32_t)((wn*64 + (lane&15))*ASTR + (lane>>4)*8)*2;
    const int r_ld = tid >> 3, c_ld = tid & 7;   // 16 rows per pass, 8 passes

    float acc[4][8][4];
    #pragma unroll
    for(int mt=0;mt<4;mt++)
        #pragma unroll
        for(int ntl=0;ntl<8;ntl++)
            #pragma unroll
            for(int e=0;e<4;e++) acc[mt][ntl][e] = 0.f;

    // prologue: chunk 0 -> stage 0
    {
        uint32_t da = smb, db = smb + CHUNK_B;
        #pragma unroll
        for(int i=0;i<8;i++){
            int r = r_ld + i*16;
            cpasync16(da + r*(ASTR*2) + c_ld*16, g_kb + (size_t)(row0+r)*KDIM + c_ld*8);
            cpasync16(db + r*(ASTR*2) + c_ld*16, g_pb + (size_t)(col0+r)*KDIM + c_ld*8);
        }
        asm volatile("cp.async.commit_group;" ::: "memory");
    }

    #pragma unroll 1
    for(int q=0; q<TOTCHK; q++){
        asm volatile("cp.async.wait_group 0;" ::: "memory");
        __syncthreads();
        // issue next chunk (overlaps this chunk's MMAs)
        if(q+1 < TOTCHK){
            const int q2 = q+1;
            const int ko2 = (q2 & 3)*KC;
            const int cb2 = col0 + (q2>>2)*BN;
            uint32_t da = smb + (uint32_t)(q2&1)*BUF_B, db = da + CHUNK_B;
            #pragma unroll
            for(int i=0;i<8;i++){
                int r = r_ld + i*16;
                cpasync16(da + r*(ASTR*2) + c_ld*16, g_kb + (size_t)(row0+r)*KDIM + ko2 + c_ld*8);
                cpasync16(db + r*(ASTR*2) + c_ld*16, g_pb + (size_t)(cb2 +r)*KDIM + ko2 + c_ld*8);
            }
            asm volatile("cp.async.commit_group;" ::: "memory");
        }

        const uint32_t ab = smb + (uint32_t)(q&1)*BUF_B;
        const uint32_t bb = ab + CHUNK_B;

        // fragment double-buffer across 4 k-steps
        uint32_t af[2][4][4], bf[2][4][4];
        #pragma unroll
        for(int mt=0;mt<4;mt++)
            ldsm4(af[0][mt][0],af[0][mt][1],af[0][mt][2],af[0][mt][3],
                  ab + a_off + (uint32_t)(mt*16*ASTR*2));
        #pragma unroll
        for(int bt=0;bt<4;bt++)
            ldsm4(bf[0][bt][0],bf[0][bt][1],bf[0][bt][2],bf[0][bt][3],
                  bb + b_off + (uint32_t)(bt*16*ASTR*2));

        #pragma unroll
        for(int ks=0; ks<4; ks++){
            const int cur = ks & 1, nxt = cur ^ 1;
            if(ks < 3){
                #pragma unroll
                for(int mt=0;mt<4;mt++)
                    ldsm4(af[nxt][mt][0],af[nxt][mt][1],af[nxt][mt][2],af[nxt][mt][3],
                          ab + a_off + (uint32_t)(mt*16*ASTR*2 + (ks+1)*32));
                #pragma unroll
                for(int bt=0;bt<4;bt++)
                    ldsm4(bf[nxt][bt][0],bf[nxt][bt][1],bf[nxt][bt][2],bf[nxt][bt][3],
                          bb + b_off + (uint32_t)(bt*16*ASTR*2 + (ks+1)*32));
            }
            #pragma unroll
            for(int mt=0;mt<4;mt++){
                #pragma unroll
                for(int bt=0;bt<4;bt++){
                    mma16816(acc[mt][bt*2  ], af[cur][mt], bf[cur][bt][0], bf[cur][bt][2]);
                    mma16816(acc[mt][bt*2+1], af[cur][mt], bf[cur][bt][1], bf[cur][bt][3]);
                }
            }
        }

        if((q & 3) == 3){
            const int colbase = col0 + (q>>2)*BN;
            #pragma unroll
            for(int mt=0;mt<4;mt++){
                const int ra = wm*64 + mt*16 + (lane>>2);
                const float ta = s_thr[ra], tb = s_thr[ra+8];
                #pragma unroll
                for(int ntl=0;ntl<8;ntl++){
                    const int c = colbase + wn*64 + ntl*8 + (lane&3)*2;
                    if(acc[mt][ntl][0] > ta){
                        int pos = atomicAdd(&g_cnt[row0+ra], 1);
                        if(pos < CAP) g_cand[(size_t)(row0+ra)*CAP + pos] = c;
                    }
                    if(acc[mt][ntl][1] > ta){
                        int pos = atomicAdd(&g_cnt[row0+ra], 1);
                        if(pos < CAP) g_cand[(size_t)(row0+ra)*CAP + pos] = c+1;
                    }
                    if(acc[mt][ntl][2] > tb){
                        int pos = atomicAdd(&g_cnt[row0+ra+8], 1);
                        if(pos < CAP) g_cand[(size_t)(row0+ra+8)*CAP + pos] = c;
                    }
                    if(acc[mt][ntl][3] > tb){
                        int pos = atomicAdd(&g_cnt[row0+ra+8], 1);
                        if(pos < CAP) g_cand[(size_t)(row0+ra+8)*CAP + pos] = c+1;
                    }
                    acc[mt][ntl][0] = 0.f; acc[mt][ntl][1] = 0.f;
                    acc[mt][ntl][2] = 0.f; acc[mt][ntl][3] = 0.f;
                }
            }
        }
    }
}

// ============================================================
// K2: exact fp32 rescore -> warp-register top-32 -> retrieved/delta
// ============================================================
__global__ void k_merge(const float* __restrict__ keys,
                        const float* __restrict__ proj,
                        const float* __restrict__ targets,
                        const float* __restrict__ memv,
                        float* __restrict__ out){
    __shared__ int   scand[CAP];
    __shared__ float sscore[CAP];
    __shared__ float skey[KDIM];
    __shared__ int   stp[SPARS];

    const int tid = threadIdx.x, lane = tid & 31, w = tid >> 5;
    const int row = blockIdx.x;
    const int n = min(g_cnt[row], CAP);

    for(int i=tid; i<n; i+=TPB) scand[i] = g_cand[(size_t)row*CAP + i];
    skey[tid] = keys[(size_t)row*KDIM + tid];
    __syncthreads();

    for(int ci=w; ci<n; ci+=8){
        const float4* pr = (const float4*)(proj + (size_t)scand[ci]*KDIM);
        float4 p0 = pr[lane*2], p1 = pr[lane*2+1];
        float4 k0 = ((const float4*)skey)[lane*2], k1 = ((const float4*)skey)[lane*2+1];
        float s = p0.x*k0.x + p0.y*k0.y + p0.z*k0.z + p0.w*k0.w
                + p1.x*k1.x + p1.y*k1.y + p1.z*k1.z + p1.w*k1.w;
        #pragma unroll
        for(int off=16; off; off>>=1) s += __shfl_xor_sync(0xffffffffu, s, off);
        if(lane == 0) sscore[ci] = s;
    }
    __syncthreads();

    if(w == 0){
        float lv[16]; int li[16];
        #pragma unroll
        for(int j=0;j<16;j++){
            int p = j*32 + lane;
            if(p < n){ lv[j] = sscore[p]; li[j] = scand[p]; }
            else     { lv[j] = -FLT_MAX;  li[j] = 0x7fffffff; }
        }
        for(int it=0; it<SPARS; it++){
            float bm = lv[0]; int bi = li[0], bj = 0;
            #pragma unroll
            for(int j=1;j<16;j++){
                if(lv[j] > bm || (lv[j] == bm && li[j] < bi)){ bm = lv[j]; bi = li[j]; bj = j; }
            }
            float gm = bm; int gi = bi;
            #pragma unroll
            for(int off=16; off; off>>=1){
                float om = __shfl_xor_sync(0xffffffffu, gm, off);
                int   oi = __shfl_xor_sync(0xffffffffu, gi, off);
                if(om > gm || (om == gm && oi < gi)){ gm = om; gi = oi; }
            }
            if(gm == bm && gi == bi){
                lv[bj] = -FLT_MAX; li[bj] = 0x7fffffff;
            }
            if(lane == 0){ stp[it] = gi; g_topk[row*SPARS + it] = gi; }
        }
    }
    __syncthreads();

    if(tid < VDIM){
        float s = 0.f;
        for(int j=0; j<SPARS; j++) s += memv[(size_t)stp[j]*VDIM + tid];
        out[(size_t)row*VDIM + tid] = s;
        g_delta[row*VDIM + tid] = (targets[(size_t)row*VDIM + tid] - s) * (0.1f/32.0f);
    }
}

// ============================================================
__global__ void k_copy(const float* __restrict__ memv, float* __restrict__ out){
    int i = blockIdx.x*blockDim.x + threadIdx.x;
    ((float4*)out)[B_ROWS*VDIM/4 + i] = ((const float4*)memv)[i];
}

__global__ void k_scatter(float* __restrict__ out){
    int g = blockIdx.x*blockDim.x + threadIdx.x;
    int b = g >> 5;
    int idx = g_topk[g];
    float* dst = out + (size_t)(B_ROWS + idx)*VDIM;
    const float* d = &g_delta[b*VDIM];
    #pragma unroll
    for(int vv=0; vv<VDIM; vv++) atomicAdd(dst+vv, d[vv]);
}

// ============================================================
extern "C" void kernel_launch(void* const* d_in, const int* in_sizes, int n_in,
                              void* d_out, int out_size){
    const float* keys    = (const float*)d_in[0];
    const float* targets = (const float*)d_in[1];
    const float* proj    = (const float*)d_in[2];
    const float* memv    = (const float*)d_in[3];
    float* out = (float*)d_out;

    cudaFuncSetAttribute(k_scores, cudaFuncAttributeMaxDynamicSharedMemorySize, SMEM_TOTAL);

    // k_scores at launch position 4 (where ncu capture lands)
    k_cvt   <<<(NK4+NP4)/TPB, TPB>>>(keys, proj);
    k_copy  <<<(MEM*VDIM/4)/TPB, TPB>>>(memv, out);
    k_thr   <<<(B_ROWS*32)/TPB, TPB>>>(keys);
    k_scores<<<dim3(B_ROWS/BM, SPLITS), TPB1, SMEM_TOTAL>>>();
    k_merge <<<B_ROWS, TPB>>>(keys, proj, targets, memv, out);
    k_scatter<<<(B_ROWS*SPARS)/TPB, TPB>>>(out);
}

// round 8
// speedup vs baseline: 1.2408x; 1.2408x over previous
#include <cuda_runtime.h>
#include <cuda_bf16.h>
#include <cfloat>
#include <cstdint>

#define B_ROWS 4096
#define KDIM   256
#define MEM    65536
#define VDIM   8
#define SPARS  32
#define TPB    256
#define BM     128
#define BN     128
#define KC     64
#define SPLITS 64
#define COLS_SPLIT (MEM/SPLITS)   // 1024
#define NTILES (COLS_SPLIT/BN)    // 8
#define NCHK   (KDIM/KC)          // 4
#define TOTCHK (NTILES*NCHK)      // 32
#define CAP    512
#define ZTH    2.95f

// smem: 3 stages x (A chunk + B chunk), chunk = 128 rows x 72 bf16
#define ASTR    72
#define CHUNK_B (BM*ASTR*2)        // 18432
#define BUF_B   (2*CHUNK_B)        // 36864
#define SM_THR  (3*BUF_B)          // 110592
#define SMEM_TOTAL (SM_THR + BM*4) // 111104 -> 2 CTAs/SM

// ---- device scratch ----
__device__ __align__(16) __nv_bfloat16 g_kb[B_ROWS*KDIM];
__device__ __align__(16) __nv_bfloat16 g_pb[MEM*KDIM];
__device__ float g_thr[B_ROWS];
__device__ int   g_cnt[B_ROWS];
__device__ int   g_cand[B_ROWS*CAP];
__device__ int   g_topk[B_ROWS*SPARS];
__device__ float g_delta[B_ROWS*VDIM];

__device__ __forceinline__ uint32_t smem_u32(const void* p){
    uint32_t a;
    asm("{ .reg .u64 t; cvta.to.shared.u64 t, %1; cvt.u32.u64 %0, t; }" : "=r"(a) : "l"(p));
    return a;
}
__device__ __forceinline__ void cpasync16(uint32_t dst, const void* src){
    asm volatile("cp.async.cg.shared.global [%0], [%1], 16;" :: "r"(dst), "l"(src));
}
__device__ __forceinline__ void ldsm4(uint32_t &r0, uint32_t &r1, uint32_t &r2, uint32_t &r3,
                                      uint32_t addr){
    asm volatile("ldmatrix.sync.aligned.m8n8.x4.shared.b16 {%0,%1,%2,%3}, [%4];"
                 : "=r"(r0), "=r"(r1), "=r"(r2), "=r"(r3) : "r"(addr));
}
__device__ __forceinline__ void mma16816(float* c,
                                         const uint32_t* a,
                                         uint32_t b0, uint32_t b1){
    asm volatile(
        "mma.sync.aligned.m16n8k16.row.col.f32.bf16.bf16.f32 "
        "{%0,%1,%2,%3}, {%4,%5,%6,%7}, {%8,%9}, {%0,%1,%2,%3};"
        : "+f"(c[0]), "+f"(c[1]), "+f"(c[2]), "+f"(c[3])
        : "r"(a[0]), "r"(a[1]), "r"(a[2]), "r"(a[3]), "r"(b0), "r"(b1));
}

// ============================================================
// K0a: fp32 -> bf16
// ============================================================
#define NK4 (B_ROWS*KDIM/4)
#define NP4 (MEM*KDIM/4)
__global__ void k_cvt(const float* __restrict__ keys, const float* __restrict__ proj){
    int gid = blockIdx.x*blockDim.x + threadIdx.x;
    if(gid < NK4){
        float4 v = ((const float4*)keys)[gid];
        __nv_bfloat162 lo = __floats2bfloat162_rn(v.x, v.y);
        __nv_bfloat162 hi = __floats2bfloat162_rn(v.z, v.w);
        ((uint2*)g_kb)[gid] = make_uint2(*(uint32_t*)&lo, *(uint32_t*)&hi);
    } else {
        int j = gid - NK4;
        float4 v = ((const float4*)proj)[j];
        __nv_bfloat162 lo = __floats2bfloat162_rn(v.x, v.y);
        __nv_bfloat162 hi = __floats2bfloat162_rn(v.z, v.w);
        ((uint2*)g_pb)[j] = make_uint2(*(uint32_t*)&lo, *(uint32_t*)&hi);
    }
}

// ============================================================
// K0b: per-row threshold + zero counters
// ============================================================
__global__ void k_thr(const float* __restrict__ keys){
    int gt = blockIdx.x*blockDim.x + threadIdx.x;
    int gw = gt >> 5, lane = gt & 31;
    if(gw >= B_ROWS) return;
    float s = 0.f;
    #pragma unroll
    for(int i=0;i<KDIM/32;i++){
        float v = keys[(size_t)gw*KDIM + i*32 + lane];
        s += v*v;
    }
    #pragma unroll
    for(int off=16; off; off>>=1) s += __shfl_xor_sync(0xffffffffu, s, off);
    if(lane == 0){
        g_thr[gw] = ZTH * sqrtf(s) * (1.0f/16.0f);
        g_cnt[gw] = 0;
    }
}

// ============================================================
// K1: bf16 mma.sync GEMM, 8 warps x (64x32) tiles, 3-stage pipeline
// grid (32, 64), block 256, 2 CTAs/SM
// ============================================================
__global__ __launch_bounds__(TPB,2)
void k_scores(){
    extern __shared__ char sm[];
    float* s_thr = (float*)(sm + SM_THR);
    const uint32_t smb = smem_u32(sm);

    const int tid  = threadIdx.x;
    const int lane = tid & 31;
    const int w    = tid >> 5;
    const int wm   = w >> 2;         // 0..1
    const int wn   = w & 3;          // 0..3
    const int row0 = blockIdx.x * BM;
    const int col0 = blockIdx.y * COLS_SPLIT;

    if(tid < BM) s_thr[tid] = g_thr[row0 + tid];

    const uint32_t a_off = (uint32_t)((wm*64 + (lane&15))*ASTR + (lane>>4)*8)*2;
    const uint32_t b_off = (uint32_t)((wn*32 + (lane&15))*ASTR + (lane>>4)*8)*2;
    const int r_ld = tid >> 3, c_ld = tid & 7;   // 32 rows per pass, 4 passes

    float acc[4][4][4];
    #pragma unroll
    for(int mt=0;mt<4;mt++)
        #pragma unroll
        for(int ntl=0;ntl<4;ntl++)
            #pragma unroll
            for(int e=0;e<4;e++) acc[mt][ntl][e] = 0.f;

    // prologue: chunks 0,1 -> stages 0,1
    #pragma unroll
    for(int p=0; p<2; p++){
        const int ko = (p & 3)*KC;
        uint32_t da = smb + (uint32_t)p*BUF_B, db = da + CHUNK_B;
        #pragma unroll
        for(int i=0;i<4;i++){
            int r = r_ld + i*32;
            cpasync16(da + r*(ASTR*2) + c_ld*16, g_kb + (size_t)(row0+r)*KDIM + ko + c_ld*8);
            cpasync16(db + r*(ASTR*2) + c_ld*16, g_pb + (size_t)(col0+r)*KDIM + ko + c_ld*8);
        }
        asm volatile("cp.async.commit_group;" ::: "memory");
    }

    #pragma unroll 1
    for(int q=0; q<TOTCHK; q++){
        if(q+1 < TOTCHK){
            asm volatile("cp.async.wait_group 1;" ::: "memory");
        } else {
            asm volatile("cp.async.wait_group 0;" ::: "memory");
        }
        __syncthreads();
        // issue chunk q+2 into stage (q+2)%3 (fully decoupled from this chunk)
        if(q+2 < TOTCHK){
            const int q2 = q+2;
            const int ko2 = (q2 & 3)*KC;
            const int cb2 = col0 + (q2>>2)*BN;
            uint32_t da = smb + (uint32_t)(q2%3)*BUF_B, db = da + CHUNK_B;
            #pragma unroll
            for(int i=0;i<4;i++){
                int r = r_ld + i*32;
                cpasync16(da + r*(ASTR*2) + c_ld*16, g_kb + (size_t)(row0+r)*KDIM + ko2 + c_ld*8);
                cpasync16(db + r*(ASTR*2) + c_ld*16, g_pb + (size_t)(cb2 +r)*KDIM + ko2 + c_ld*8);
            }
            asm volatile("cp.async.commit_group;" ::: "memory");
        }

        const uint32_t ab = smb + (uint32_t)(q%3)*BUF_B;
        const uint32_t bb = ab + CHUNK_B;
        #pragma unroll
        for(int ks=0; ks<4; ks++){
            uint32_t af[4][4];
            #pragma unroll
            for(int mt=0;mt<4;mt++)
                ldsm4(af[mt][0],af[mt][1],af[mt][2],af[mt][3],
                      ab + a_off + (uint32_t)(mt*16*ASTR*2 + ks*32));
            uint32_t bf[2][4];
            #pragma unroll
            for(int bt=0;bt<2;bt++)
                ldsm4(bf[bt][0],bf[bt][1],bf[bt][2],bf[bt][3],
                      bb + b_off + (uint32_t)(bt*16*ASTR*2 + ks*32));
            #pragma unroll
            for(int mt=0;mt<4;mt++){
                #pragma unroll
                for(int bt=0;bt<2;bt++){
                    mma16816(acc[mt][bt*2  ], af[mt], bf[bt][0], bf[bt][2]);
                    mma16816(acc[mt][bt*2+1], af[mt], bf[bt][1], bf[bt][3]);
                }
            }
        }

        if((q & 3) == 3){
            const int colbase = col0 + (q>>2)*BN;
            #pragma unroll
            for(int mt=0;mt<4;mt++){
                const int ra = wm*64 + mt*16 + (lane>>2);
                const float ta = s_thr[ra], tb = s_thr[ra+8];
                #pragma unroll
                for(int ntl=0;ntl<4;ntl++){
                    const int c = colbase + wn*32 + ntl*8 + (lane&3)*2;
                    if(acc[mt][ntl][0] > ta){
                        int pos = atomicAdd(&g_cnt[row0+ra], 1);
                        if(pos < CAP) g_cand[(size_t)(row0+ra)*CAP + pos] = c;
                    }
                    if(acc[mt][ntl][1] > ta){
                        int pos = atomicAdd(&g_cnt[row0+ra], 1);
                        if(pos < CAP) g_cand[(size_t)(row0+ra)*CAP + pos] = c+1;
                    }
                    if(acc[mt][ntl][2] > tb){
                        int pos = atomicAdd(&g_cnt[row0+ra+8], 1);
                        if(pos < CAP) g_cand[(size_t)(row0+ra+8)*CAP + pos] = c;
                    }
                    if(acc[mt][ntl][3] > tb){
                        int pos = atomicAdd(&g_cnt[row0+ra+8], 1);
                        if(pos < CAP) g_cand[(size_t)(row0+ra+8)*CAP + pos] = c+1;
                    }
                    acc[mt][ntl][0] = 0.f; acc[mt][ntl][1] = 0.f;
                    acc[mt][ntl][2] = 0.f; acc[mt][ntl][3] = 0.f;
                }
            }
        }
    }
}

// ============================================================
// K2: exact fp32 rescore -> warp-register top-32 -> retrieved/delta
// ============================================================
__global__ void k_merge(const float* __restrict__ keys,
                        const float* __restrict__ proj,
                        const float* __restrict__ targets,
                        const float* __restrict__ memv,
                        float* __restrict__ out){
    __shared__ int   scand[CAP];
    __shared__ float sscore[CAP];
    __shared__ float skey[KDIM];
    __shared__ int   stp[SPARS];

    const int tid = threadIdx.x, lane = tid & 31, w = tid >> 5;
    const int row = blockIdx.x;
    const int n = min(g_cnt[row], CAP);

    for(int i=tid; i<n; i+=TPB) scand[i] = g_cand[(size_t)row*CAP + i];
    skey[tid] = keys[(size_t)row*KDIM + tid];
    __syncthreads();

    for(int ci=w; ci<n; ci+=8){
        const float4* pr = (const float4*)(proj + (size_t)scand[ci]*KDIM);
        float4 p0 = pr[lane*2], p1 = pr[lane*2+1];
        float4 k0 = ((const float4*)skey)[lane*2], k1 = ((const float4*)skey)[lane*2+1];
        float s = p0.x*k0.x + p0.y*k0.y + p0.z*k0.z + p0.w*k0.w
                + p1.x*k1.x + p1.y*k1.y + p1.z*k1.z + p1.w*k1.w;
        #pragma unroll
        for(int off=16; off; off>>=1) s += __shfl_xor_sync(0xffffffffu, s, off);
        if(lane == 0) sscore[ci] = s;
    }
    __syncthreads();

    if(w == 0){
        float lv[16]; int li[16];
        #pragma unroll
        for(int j=0;j<16;j++){
            int p = j*32 + lane;
            if(p < n){ lv[j] = sscore[p]; li[j] = scand[p]; }
            else     { lv[j] = -FLT_MAX;  li[j] = 0x7fffffff; }
        }
        for(int it=0; it<SPARS; it++){
            float bm = lv[0]; int bi = li[0], bj = 0;
            #pragma unroll
            for(int j=1;j<16;j++){
                if(lv[j] > bm || (lv[j] == bm && li[j] < bi)){ bm = lv[j]; bi = li[j]; bj = j; }
            }
            float gm = bm; int gi = bi;
            #pragma unroll
            for(int off=16; off; off>>=1){
                float om = __shfl_xor_sync(0xffffffffu, gm, off);
                int   oi = __shfl_xor_sync(0xffffffffu, gi, off);
                if(om > gm || (om == gm && oi < gi)){ gm = om; gi = oi; }
            }
            if(gm == bm && gi == bi){
                lv[bj] = -FLT_MAX; li[bj] = 0x7fffffff;
            }
            if(lane == 0){ stp[it] = gi; g_topk[row*SPARS + it] = gi; }
        }
    }
    __syncthreads();

    if(tid < VDIM){
        float s = 0.f;
        for(int j=0; j<SPARS; j++) s += memv[(size_t)stp[j]*VDIM + tid];
        out[(size_t)row*VDIM + tid] = s;
        g_delta[row*VDIM + tid] = (targets[(size_t)row*VDIM + tid] - s) * (0.1f/32.0f);
    }
}

// ============================================================
__global__ void k_copy(const float* __restrict__ memv, float* __restrict__ out){
    int i = blockIdx.x*blockDim.x + threadIdx.x;
    ((float4*)out)[B_ROWS*VDIM/4 + i] = ((const float4*)memv)[i];
}

__global__ void k_scatter(float* __restrict__ out){
    int g = blockIdx.x*blockDim.x + threadIdx.x;
    int b = g >> 5;
    int idx = g_topk[g];
    float* dst = out + (size_t)(B_ROWS + idx)*VDIM;
    const float* d = &g_delta[b*VDIM];
    #pragma unroll
    for(int vv=0; vv<VDIM; vv++) atomicAdd(dst+vv, d[vv]);
}

// ============================================================
extern "C" void kernel_launch(void* const* d_in, const int* in_sizes, int n_in,
                              void* d_out, int out_size){
    const float* keys    = (const float*)d_in[0];
    const float* targets = (const float*)d_in[1];
    const float* proj    = (const float*)d_in[2];
    const float* memv    = (const float*)d_in[3];
    float* out = (float*)d_out;

    cudaFuncSetAttribute(k_scores, cudaFuncAttributeMaxDynamicSharedMemorySize, SMEM_TOTAL);

    // k_scores at launch position 4 (where ncu capture lands)
    k_cvt   <<<(NK4+NP4)/TPB, TPB>>>(keys, proj);
    k_copy  <<<(MEM*VDIM/4)/TPB, TPB>>>(memv, out);
    k_thr   <<<(B_ROWS*32)/TPB, TPB>>>(keys);
    k_scores<<<dim3(B_ROWS/BM, SPLITS), TPB, SMEM_TOTAL>>>();
    k_merge <<<B_ROWS, TPB>>>(keys, proj, targets, memv, out);
    k_scatter<<<(B_ROWS*SPARS)/TPB, TPB>>>(out);
}

// round 9
// speedup vs baseline: 1.2676x; 1.0216x over previous
#include <cuda_runtime.h>
#include <cuda_fp16.h>
#include <cfloat>
#include <cstdint>

#define B_ROWS 4096
#define KDIM   256
#define MEM    65536
#define VDIM   8
#define SPARS  32
#define TPB    256
#define BM     128
#define BN     128
#define KC     64
#define SPLITS 64
#define COLS_SPLIT (MEM/SPLITS)   // 1024
#define NTILES (COLS_SPLIT/BN)    // 8
#define NCHK   (KDIM/KC)          // 4
#define TOTCHK (NTILES*NCHK)      // 32
#define CAP    512
#define ZTH    2.95f

// smem: 3 stages x (A chunk + B chunk), chunk = 128 rows x 72 fp16
#define ASTR    72
#define CHUNK_B (BM*ASTR*2)        // 18432
#define BUF_B   (2*CHUNK_B)        // 36864
#define SM_THR  (3*BUF_B)          // 110592
#define SMEM_TOTAL (SM_THR + BM*4) // 111104 -> 2 CTAs/SM

// ---- device scratch ----
__device__ __align__(16) __half g_kb[B_ROWS*KDIM];
__device__ __align__(16) __half g_pb[MEM*KDIM];
__device__ float g_thr[B_ROWS];
__device__ int   g_cnt[B_ROWS];
__device__ int   g_cand[B_ROWS*CAP];
__device__ int   g_topk[B_ROWS*SPARS];
__device__ float g_delta[B_ROWS*VDIM];

__device__ __forceinline__ uint32_t smem_u32(const void* p){
    uint32_t a;
    asm("{ .reg .u64 t; cvta.to.shared.u64 t, %1; cvt.u32.u64 %0, t; }" : "=r"(a) : "l"(p));
    return a;
}
__device__ __forceinline__ void cpasync16(uint32_t dst, const void* src){
    asm volatile("cp.async.cg.shared.global [%0], [%1], 16;" :: "r"(dst), "l"(src));
}
__device__ __forceinline__ void ldsm4(uint32_t &r0, uint32_t &r1, uint32_t &r2, uint32_t &r3,
                                      uint32_t addr){
    asm volatile("ldmatrix.sync.aligned.m8n8.x4.shared.b16 {%0,%1,%2,%3}, [%4];"
                 : "=r"(r0), "=r"(r1), "=r"(r2), "=r"(r3) : "r"(addr));
}
// f16 accumulate: D,C = 2x f16x2 regs
__device__ __forceinline__ void mma16816h(uint32_t* c,
                                          const uint32_t* a,
                                          uint32_t b0, uint32_t b1){
    asm volatile(
        "mma.sync.aligned.m16n8k16.row.col.f16.f16.f16.f16 "
        "{%0,%1}, {%2,%3,%4,%5}, {%6,%7}, {%0,%1};"
        : "+r"(c[0]), "+r"(c[1])
        : "r"(a[0]), "r"(a[1]), "r"(a[2]), "r"(a[3]), "r"(b0), "r"(b1));
}

// ============================================================
// K0a: fp32 -> fp16
// ============================================================
#define NK4 (B_ROWS*KDIM/4)
#define NP4 (MEM*KDIM/4)
__global__ void k_cvt(const float* __restrict__ keys, const float* __restrict__ proj){
    int gid = blockIdx.x*blockDim.x + threadIdx.x;
    if(gid < NK4){
        float4 v = ((const float4*)keys)[gid];
        __half2 lo = __floats2half2_rn(v.x, v.y);
        __half2 hi = __floats2half2_rn(v.z, v.w);
        ((uint2*)g_kb)[gid] = make_uint2(*(uint32_t*)&lo, *(uint32_t*)&hi);
    } else {
        int j = gid - NK4;
        float4 v = ((const float4*)proj)[j];
        __half2 lo = __floats2half2_rn(v.x, v.y);
        __half2 hi = __floats2half2_rn(v.z, v.w);
        ((uint2*)g_pb)[j] = make_uint2(*(uint32_t*)&lo, *(uint32_t*)&hi);
    }
}

// ============================================================
// K0b: per-row threshold + zero counters
// ============================================================
__global__ void k_thr(const float* __restrict__ keys){
    int gt = blockIdx.x*blockDim.x + threadIdx.x;
    int gw = gt >> 5, lane = gt & 31;
    if(gw >= B_ROWS) return;
    float s = 0.f;
    #pragma unroll
    for(int i=0;i<KDIM/32;i++){
        float v = keys[(size_t)gw*KDIM + i*32 + lane];
        s += v*v;
    }
    #pragma unroll
    for(int off=16; off; off>>=1) s += __shfl_xor_sync(0xffffffffu, s, off);
    if(lane == 0){
        g_thr[gw] = ZTH * sqrtf(s) * (1.0f/16.0f);
        g_cnt[gw] = 0;
    }
}

// ============================================================
// K1: fp16 mma.sync GEMM (f16 acc), 8 warps x (64x32) tiles,
// 3-stage smem pipeline + fragment double-buffer
// grid (32, 64), block 256, 2 CTAs/SM
// ============================================================
__global__ __launch_bounds__(TPB,2)
void k_scores(){
    extern __shared__ char sm[];
    float* s_thr = (float*)(sm + SM_THR);
    const uint32_t smb = smem_u32(sm);

    const int tid  = threadIdx.x;
    const int lane = tid & 31;
    const int w    = tid >> 5;
    const int wm   = w >> 2;         // 0..1
    const int wn   = w & 3;          // 0..3
    const int row0 = blockIdx.x * BM;
    const int col0 = blockIdx.y * COLS_SPLIT;

    if(tid < BM) s_thr[tid] = g_thr[row0 + tid];

    const uint32_t a_off = (uint32_t)((wm*64 + (lane&15))*ASTR + (lane>>4)*8)*2;
    const uint32_t b_off = (uint32_t)((wn*32 + (lane&15))*ASTR + (lane>>4)*8)*2;
    const int r_ld = tid >> 3, c_ld = tid & 7;

    // f16x2 accumulators: [mt][ntl][2]
    uint32_t acc[4][4][2];
    #pragma unroll
    for(int mt=0;mt<4;mt++)
        #pragma unroll
        for(int ntl=0;ntl<4;ntl++){ acc[mt][ntl][0]=0u; acc[mt][ntl][1]=0u; }

    // prologue: chunks 0,1 -> stages 0,1
    #pragma unroll
    for(int p=0; p<2; p++){
        const int ko = (p & 3)*KC;
        uint32_t da = smb + (uint32_t)p*BUF_B, db = da + CHUNK_B;
        #pragma unroll
        for(int i=0;i<4;i++){
            int r = r_ld + i*32;
            cpasync16(da + r*(ASTR*2) + c_ld*16, g_kb + (size_t)(row0+r)*KDIM + ko + c_ld*8);
            cpasync16(db + r*(ASTR*2) + c_ld*16, g_pb + (size_t)(col0+r)*KDIM + ko + c_ld*8);
        }
        asm volatile("cp.async.commit_group;" ::: "memory");
    }

    #pragma unroll 1
    for(int q=0; q<TOTCHK; q++){
        if(q+1 < TOTCHK){
            asm volatile("cp.async.wait_group 1;" ::: "memory");
        } else {
            asm volatile("cp.async.wait_group 0;" ::: "memory");
        }
        __syncthreads();
        if(q+2 < TOTCHK){
            const int q2 = q+2;
            const int ko2 = (q2 & 3)*KC;
            const int cb2 = col0 + (q2>>2)*BN;
            uint32_t da = smb + (uint32_t)(q2%3)*BUF_B, db = da + CHUNK_B;
            #pragma unroll
            for(int i=0;i<4;i++){
                int r = r_ld + i*32;
                cpasync16(da + r*(ASTR*2) + c_ld*16, g_kb + (size_t)(row0+r)*KDIM + ko2 + c_ld*8);
                cpasync16(db + r*(ASTR*2) + c_ld*16, g_pb + (size_t)(cb2 +r)*KDIM + ko2 + c_ld*8);
            }
            asm volatile("cp.async.commit_group;" ::: "memory");
        }

        const uint32_t ab = smb + (uint32_t)(q%3)*BUF_B;
        const uint32_t bb = ab + CHUNK_B;

        // fragment double-buffer across the 4 k-steps
        uint32_t af[2][4][4], bf[2][2][4];
        #pragma unroll
        for(int mt=0;mt<4;mt++)
            ldsm4(af[0][mt][0],af[0][mt][1],af[0][mt][2],af[0][mt][3],
                  ab + a_off + (uint32_t)(mt*16*ASTR*2));
        #pragma unroll
        for(int bt=0;bt<2;bt++)
            ldsm4(bf[0][bt][0],bf[0][bt][1],bf[0][bt][2],bf[0][bt][3],
                  bb + b_off + (uint32_t)(bt*16*ASTR*2));

        #pragma unroll
        for(int ks=0; ks<4; ks++){
            const int cur = ks & 1, nxt = cur ^ 1;
            if(ks < 3){
                #pragma unroll
                for(int mt=0;mt<4;mt++)
                    ldsm4(af[nxt][mt][0],af[nxt][mt][1],af[nxt][mt][2],af[nxt][mt][3],
                          ab + a_off + (uint32_t)(mt*16*ASTR*2 + (ks+1)*32));
                #pragma unroll
                for(int bt=0;bt<2;bt++)
                    ldsm4(bf[nxt][bt][0],bf[nxt][bt][1],bf[nxt][bt][2],bf[nxt][bt][3],
                          bb + b_off + (uint32_t)(bt*16*ASTR*2 + (ks+1)*32));
            }
            #pragma unroll
            for(int mt=0;mt<4;mt++){
                #pragma unroll
                for(int bt=0;bt<2;bt++){
                    mma16816h(acc[mt][bt*2  ], af[cur][mt], bf[cur][bt][0], bf[cur][bt][2]);
                    mma16816h(acc[mt][bt*2+1], af[cur][mt], bf[cur][bt][1], bf[cur][bt][3]);
                }
            }
        }

        if((q & 3) == 3){
            const int colbase = col0 + (q>>2)*BN;
            #pragma unroll
            for(int mt=0;mt<4;mt++){
                const int ra = wm*64 + mt*16 + (lane>>2);
                const float ta = s_thr[ra], tb = s_thr[ra+8];
                const float tmin = fminf(ta, tb);
                #pragma unroll
                for(int ntl=0;ntl<4;ntl++){
                    const int c = colbase + wn*32 + ntl*8 + (lane&3)*2;
                    __half2 h0 = *(__half2*)&acc[mt][ntl][0];   // rows ra   : cols c, c+1
                    __half2 h1 = *(__half2*)&acc[mt][ntl][1];   // rows ra+8 : cols c, c+1
                    __half2 hm = __hmax2(h0, h1);
                    float fm = fmaxf(__low2float(hm), __high2float(hm));
                    if(fm > tmin){   // rare slow path (~0.1%)
                        float v0 = __low2float(h0), v1 = __high2float(h0);
                        float v2 = __low2float(h1), v3 = __high2float(h1);
                        if(v0 > ta){
                            int pos = atomicAdd(&g_cnt[row0+ra], 1);
                            if(pos < CAP) g_cand[(size_t)(row0+ra)*CAP + pos] = c;
                        }
                        if(v1 > ta){
                            int pos = atomicAdd(&g_cnt[row0+ra], 1);
                            if(pos < CAP) g_cand[(size_t)(row0+ra)*CAP + pos] = c+1;
                        }
                        if(v2 > tb){
                            int pos = atomicAdd(&g_cnt[row0+ra+8], 1);
                            if(pos < CAP) g_cand[(size_t)(row0+ra+8)*CAP + pos] = c;
                        }
                        if(v3 > tb){
                            int pos = atomicAdd(&g_cnt[row0+ra+8], 1);
                            if(pos < CAP) g_cand[(size_t)(row0+ra+8)*CAP + pos] = c+1;
                        }
                    }
                    acc[mt][ntl][0] = 0u; acc[mt][ntl][1] = 0u;
                }
            }
        }
    }
}

// ============================================================
// K2: exact fp32 rescore -> warp-register top-32 -> retrieved/delta
// ============================================================
__global__ void k_merge(const float* __restrict__ keys,
                        const float* __restrict__ proj,
                        const float* __restrict__ targets,
                        const float* __restrict__ memv,
                        float* __restrict__ out){
    __shared__ int   scand[CAP];
    __shared__ float sscore[CAP];
    __shared__ float skey[KDIM];
    __shared__ int   stp[SPARS];

    const int tid = threadIdx.x, lane = tid & 31, w = tid >> 5;
    const int row = blockIdx.x;
    const int n = min(g_cnt[row], CAP);

    for(int i=tid; i<n; i+=TPB) scand[i] = g_cand[(size_t)row*CAP + i];
    skey[tid] = keys[(size_t)row*KDIM + tid];
    __syncthreads();

    for(int ci=w; ci<n; ci+=8){
        const float4* pr = (const float4*)(proj + (size_t)scand[ci]*KDIM);
        float4 p0 = pr[lane*2], p1 = pr[lane*2+1];
        float4 k0 = ((const float4*)skey)[lane*2], k1 = ((const float4*)skey)[lane*2+1];
        float s = p0.x*k0.x + p0.y*k0.y + p0.z*k0.z + p0.w*k0.w
                + p1.x*k1.x + p1.y*k1.y + p1.z*k1.z + p1.w*k1.w;
        #pragma unroll
        for(int off=16; off; off>>=1) s += __shfl_xor_sync(0xffffffffu, s, off);
        if(lane == 0) sscore[ci] = s;
    }
    __syncthreads();

    if(w == 0){
        float lv[16]; int li[16];
        #pragma unroll
        for(int j=0;j<16;j++){
            int p = j*32 + lane;
            if(p < n){ lv[j] = sscore[p]; li[j] = scand[p]; }
            else     { lv[j] = -FLT_MAX;  li[j] = 0x7fffffff; }
        }
        for(int it=0; it<SPARS; it++){
            float bm = lv[0]; int bi = li[0], bj = 0;
            #pragma unroll
            for(int j=1;j<16;j++){
                if(lv[j] > bm || (lv[j] == bm && li[j] < bi)){ bm = lv[j]; bi = li[j]; bj = j; }
            }
            float gm = bm; int gi = bi;
            #pragma unroll
            for(int off=16; off; off>>=1){
                float om = __shfl_xor_sync(0xffffffffu, gm, off);
                int   oi = __shfl_xor_sync(0xffffffffu, gi, off);
                if(om > gm || (om == gm && oi < gi)){ gm = om; gi = oi; }
            }
            if(gm == bm && gi == bi){
                lv[bj] = -FLT_MAX; li[bj] = 0x7fffffff;
            }
            if(lane == 0){ stp[it] = gi; g_topk[row*SPARS + it] = gi; }
        }
    }
    __syncthreads();

    if(tid < VDIM){
        float s = 0.f;
        for(int j=0; j<SPARS; j++) s += memv[(size_t)stp[j]*VDIM + tid];
        out[(size_t)row*VDIM + tid] = s;
        g_delta[row*VDIM + tid] = (targets[(size_t)row*VDIM + tid] - s) * (0.1f/32.0f);
    }
}

// ============================================================
__global__ void k_copy(const float* __restrict__ memv, float* __restrict__ out){
    int i = blockIdx.x*blockDim.x + threadIdx.x;
    ((float4*)out)[B_ROWS*VDIM/4 + i] = ((const float4*)memv)[i];
}

__global__ void k_scatter(float* __restrict__ out){
    int g = blockIdx.x*blockDim.x + threadIdx.x;
    int b = g >> 5;
    int idx = g_topk[g];
    float* dst = out + (size_t)(B_ROWS + idx)*VDIM;
    const float* d = &g_delta[b*VDIM];
    #pragma unroll
    for(int vv=0; vv<VDIM; vv++) atomicAdd(dst+vv, d[vv]);
}

// ============================================================
extern "C" void kernel_launch(void* const* d_in, const int* in_sizes, int n_in,
                              void* d_out, int out_size){
    const float* keys    = (const float*)d_in[0];
    const float* targets = (const float*)d_in[1];
    const float* proj    = (const float*)d_in[2];
    const float* memv    = (const float*)d_in[3];
    float* out = (float*)d_out;

    cudaFuncSetAttribute(k_scores, cudaFuncAttributeMaxDynamicSharedMemorySize, SMEM_TOTAL);

    // k_scores at launch position 4 (where ncu capture lands)
    k_cvt   <<<(NK4+NP4)/TPB, TPB>>>(keys, proj);
    k_copy  <<<(MEM*VDIM/4)/TPB, TPB>>>(memv, out);
    k_thr   <<<(B_ROWS*32)/TPB, TPB>>>(keys);
    k_scores<<<dim3(B_ROWS/BM, SPLITS), TPB, SMEM_TOTAL>>>();
    k_merge <<<B_ROWS, TPB>>>(keys, proj, targets, memv, out);
    k_scatter<<<(B_ROWS*SPARS)/TPB, TPB>>>(out);
}

// round 10
// speedup vs baseline: 1.4018x; 1.1059x over previous
#include <cuda_runtime.h>
#include <cuda_fp16.h>
#include <cfloat>
#include <cstdint>

#define B_ROWS 4096
#define KDIM   256
#define MEM    65536
#define VDIM   8
#define SPARS  32
#define TPB    256
#define BM     128
#define BN     128
#define KC     64
#define SPLITS 64
#define COLS_SPLIT (MEM/SPLITS)   // 1024
#define NTILES (COLS_SPLIT/BN)    // 8
#define NCHK   (KDIM/KC)          // 4
#define TOTCHK (NTILES*NCHK)      // 32
#define CAP    512
#define ZTH    2.95f

// smem: 2 stages x (A chunk + B chunk), chunk = 128 rows x 72 fp16
#define ASTR    72
#define CHUNK_B (BM*ASTR*2)        // 18432
#define BUF_B   (2*CHUNK_B)        // 36864
#define SM_THR  (2*BUF_B)          // 73728
#define SMEM_TOTAL (SM_THR + BM*4) // 74240 -> 3 CTAs/SM

// ---- device scratch ----
__device__ __align__(16) __half g_kb[B_ROWS*KDIM];
__device__ __align__(16) __half g_pb[MEM*KDIM];
__device__ float g_thr[B_ROWS];
__device__ int   g_cnt[B_ROWS];
__device__ int   g_cand[B_ROWS*CAP];
__device__ int   g_topk[B_ROWS*SPARS];
__device__ float g_delta[B_ROWS*VDIM];

__device__ __forceinline__ uint32_t smem_u32(const void* p){
    uint32_t a;
    asm("{ .reg .u64 t; cvta.to.shared.u64 t, %1; cvt.u32.u64 %0, t; }" : "=r"(a) : "l"(p));
    return a;
}
__device__ __forceinline__ void cpasync16(uint32_t dst, const void* src){
    asm volatile("cp.async.cg.shared.global [%0], [%1], 16;" :: "r"(dst), "l"(src));
}
__device__ __forceinline__ void ldsm4(uint32_t &r0, uint32_t &r1, uint32_t &r2, uint32_t &r3,
                                      uint32_t addr){
    asm volatile("ldmatrix.sync.aligned.m8n8.x4.shared.b16 {%0,%1,%2,%3}, [%4];"
                 : "=r"(r0), "=r"(r1), "=r"(r2), "=r"(r3) : "r"(addr));
}
__device__ __forceinline__ void mma16816h(uint32_t* c,
                                          const uint32_t* a,
                                          uint32_t b0, uint32_t b1){
    asm volatile(
        "mma.sync.aligned.m16n8k16.row.col.f16.f16.f16.f16 "
        "{%0,%1}, {%2,%3,%4,%5}, {%6,%7}, {%0,%1};"
        : "+r"(c[0]), "+r"(c[1])
        : "r"(a[0]), "r"(a[1]), "r"(a[2]), "r"(a[3]), "r"(b0), "r"(b1));
}

// ============================================================
// K0a: fp32 -> fp16
// ============================================================
#define NK4 (B_ROWS*KDIM/4)
#define NP4 (MEM*KDIM/4)
__global__ void k_cvt(const float* __restrict__ keys, const float* __restrict__ proj){
    int gid = blockIdx.x*blockDim.x + threadIdx.x;
    if(gid < NK4){
        float4 v = ((const float4*)keys)[gid];
        __half2 lo = __floats2half2_rn(v.x, v.y);
        __half2 hi = __floats2half2_rn(v.z, v.w);
        ((uint2*)g_kb)[gid] = make_uint2(*(uint32_t*)&lo, *(uint32_t*)&hi);
    } else {
        int j = gid - NK4;
        float4 v = ((const float4*)proj)[j];
        __half2 lo = __floats2half2_rn(v.x, v.y);
        __half2 hi = __floats2half2_rn(v.z, v.w);
        ((uint2*)g_pb)[j] = make_uint2(*(uint32_t*)&lo, *(uint32_t*)&hi);
    }
}

// ============================================================
// K0b: per-row threshold + zero counters
// ============================================================
__global__ void k_thr(const float* __restrict__ keys){
    int gt = blockIdx.x*blockDim.x + threadIdx.x;
    int gw = gt >> 5, lane = gt & 31;
    if(gw >= B_ROWS) return;
    float s = 0.f;
    #pragma unroll
    for(int i=0;i<KDIM/32;i++){
        float v = keys[(size_t)gw*KDIM + i*32 + lane];
        s += v*v;
    }
    #pragma unroll
    for(int off=16; off; off>>=1) s += __shfl_xor_sync(0xffffffffu, s, off);
    if(lane == 0){
        g_thr[gw] = ZTH * sqrtf(s) * (1.0f/16.0f);
        g_cnt[gw] = 0;
    }
}

// ============================================================
// K1: fp16 mma.sync GEMM (f16 acc), 8 warps x (64x32) tiles,
// 2-stage pipeline, 3 CTAs/SM
// grid (32, 64), block 256
// ============================================================
__global__ __launch_bounds__(TPB,3)
void k_scores(){
    extern __shared__ char sm[];
    float* s_thr = (float*)(sm + SM_THR);
    const uint32_t smb = smem_u32(sm);

    const int tid  = threadIdx.x;
    const int lane = tid & 31;
    const int w    = tid >> 5;
    const int wm   = w >> 2;         // 0..1
    const int wn   = w & 3;          // 0..3
    const int row0 = blockIdx.x * BM;
    const int col0 = blockIdx.y * COLS_SPLIT;

    if(tid < BM) s_thr[tid] = g_thr[row0 + tid];

    const uint32_t a_off = (uint32_t)((wm*64 + (lane&15))*ASTR + (lane>>4)*8)*2;
    const uint32_t b_off = (uint32_t)((wn*32 + (lane&15))*ASTR + (lane>>4)*8)*2;
    const int r_ld = tid >> 3, c_ld = tid & 7;

    uint32_t acc[4][4][2];
    #pragma unroll
    for(int mt=0;mt<4;mt++)
        #pragma unroll
        for(int ntl=0;ntl<4;ntl++){ acc[mt][ntl][0]=0u; acc[mt][ntl][1]=0u; }

    // prologue: chunk 0 -> stage 0
    {
        uint32_t da = smb, db = smb + CHUNK_B;
        #pragma unroll
        for(int i=0;i<4;i++){
            int r = r_ld + i*32;
            cpasync16(da + r*(ASTR*2) + c_ld*16, g_kb + (size_t)(row0+r)*KDIM + c_ld*8);
            cpasync16(db + r*(ASTR*2) + c_ld*16, g_pb + (size_t)(col0+r)*KDIM + c_ld*8);
        }
        asm volatile("cp.async.commit_group;" ::: "memory");
    }

    #pragma unroll 1
    for(int q=0; q<TOTCHK; q++){
        asm volatile("cp.async.wait_group 0;" ::: "memory");
        __syncthreads();
        // issue chunk q+1 into the other stage (overlaps this chunk's MMAs)
        if(q+1 < TOTCHK){
            const int q2 = q+1;
            const int ko2 = (q2 & 3)*KC;
            const int cb2 = col0 + (q2>>2)*BN;
            uint32_t da = smb + (uint32_t)(q2&1)*BUF_B, db = da + CHUNK_B;
            #pragma unroll
            for(int i=0;i<4;i++){
                int r = r_ld + i*32;
                cpasync16(da + r*(ASTR*2) + c_ld*16, g_kb + (size_t)(row0+r)*KDIM + ko2 + c_ld*8);
                cpasync16(db + r*(ASTR*2) + c_ld*16, g_pb + (size_t)(cb2 +r)*KDIM + ko2 + c_ld*8);
            }
            asm volatile("cp.async.commit_group;" ::: "memory");
        }

        const uint32_t ab = smb + (uint32_t)(q&1)*BUF_B;
        const uint32_t bb = ab + CHUNK_B;
        #pragma unroll
        for(int ks=0; ks<4; ks++){
            uint32_t af[4][4];
            #pragma unroll
            for(int mt=0;mt<4;mt++)
                ldsm4(af[mt][0],af[mt][1],af[mt][2],af[mt][3],
                      ab + a_off + (uint32_t)(mt*16*ASTR*2 + ks*32));
            uint32_t bf[2][4];
            #pragma unroll
            for(int bt=0;bt<2;bt++)
                ldsm4(bf[bt][0],bf[bt][1],bf[bt][2],bf[bt][3],
                      bb + b_off + (uint32_t)(bt*16*ASTR*2 + ks*32));
            #pragma unroll
            for(int mt=0;mt<4;mt++){
                #pragma unroll
                for(int bt=0;bt<2;bt++){
                    mma16816h(acc[mt][bt*2  ], af[mt], bf[bt][0], bf[bt][2]);
                    mma16816h(acc[mt][bt*2+1], af[mt], bf[bt][1], bf[bt][3]);
                }
            }
        }

        if((q & 3) == 3){
            const int colbase = col0 + (q>>2)*BN;
            #pragma unroll
            for(int mt=0;mt<4;mt++){
                const int ra = wm*64 + mt*16 + (lane>>2);
                const float ta = s_thr[ra], tb = s_thr[ra+8];
                const float tmin = fminf(ta, tb);
                #pragma unroll
                for(int ntl=0;ntl<4;ntl++){
                    const int c = colbase + wn*32 + ntl*8 + (lane&3)*2;
                    __half2 h0 = *(__half2*)&acc[mt][ntl][0];
                    __half2 h1 = *(__half2*)&acc[mt][ntl][1];
                    __half2 hm = __hmax2(h0, h1);
                    float fm = fmaxf(__low2float(hm), __high2float(hm));
                    if(fm > tmin){
                        float v0 = __low2float(h0), v1 = __high2float(h0);
                        float v2 = __low2float(h1), v3 = __high2float(h1);
                        if(v0 > ta){
                            int pos = atomicAdd(&g_cnt[row0+ra], 1);
                            if(pos < CAP) g_cand[(size_t)(row0+ra)*CAP + pos] = c;
                        }
                        if(v1 > ta){
                            int pos = atomicAdd(&g_cnt[row0+ra], 1);
                            if(pos < CAP) g_cand[(size_t)(row0+ra)*CAP + pos] = c+1;
                        }
                        if(v2 > tb){
                            int pos = atomicAdd(&g_cnt[row0+ra+8], 1);
                            if(pos < CAP) g_cand[(size_t)(row0+ra+8)*CAP + pos] = c;
                        }
                        if(v3 > tb){
                            int pos = atomicAdd(&g_cnt[row0+ra+8], 1);
                            if(pos < CAP) g_cand[(size_t)(row0+ra+8)*CAP + pos] = c+1;
                        }
                    }
                    acc[mt][ntl][0] = 0u; acc[mt][ntl][1] = 0u;
                }
            }
        }
    }
}

// ============================================================
// K2: exact fp32 rescore -> warp-register top-32 -> retrieved/delta
// ============================================================
__global__ void k_merge(const float* __restrict__ keys,
                        const float* __restrict__ proj,
                        const float* __restrict__ targets,
                        const float* __restrict__ memv,
                        float* __restrict__ out){
    __shared__ int   scand[CAP];
    __shared__ float sscore[CAP];
    __shared__ float skey[KDIM];
    __shared__ int   stp[SPARS];

    const int tid = threadIdx.x, lane = tid & 31, w = tid >> 5;
    const int row = blockIdx.x;
    const int n = min(g_cnt[row], CAP);

    for(int i=tid; i<n; i+=TPB) scand[i] = g_cand[(size_t)row*CAP + i];
    skey[tid] = keys[(size_t)row*KDIM + tid];
    __syncthreads();

    for(int ci=w; ci<n; ci+=8){
        const float4* pr = (const float4*)(proj + (size_t)scand[ci]*KDIM);
        float4 p0 = pr[lane*2], p1 = pr[lane*2+1];
        float4 k0 = ((const float4*)skey)[lane*2], k1 = ((const float4*)skey)[lane*2+1];
        float s = p0.x*k0.x + p0.y*k0.y + p0.z*k0.z + p0.w*k0.w
                + p1.x*k1.x + p1.y*k1.y + p1.z*k1.z + p1.w*k1.w;
        #pragma unroll
        for(int off=16; off; off>>=1) s += __shfl_xor_sync(0xffffffffu, s, off);
        if(lane == 0) sscore[ci] = s;
    }
    __syncthreads();

    if(w == 0){
        float lv[16]; int li[16];
        #pragma unroll
        for(int j=0;j<16;j++){
            int p = j*32 + lane;
            if(p < n){ lv[j] = sscore[p]; li[j] = scand[p]; }
            else     { lv[j] = -FLT_MAX;  li[j] = 0x7fffffff; }
        }
        for(int it=0; it<SPARS; it++){
            float bm = lv[0]; int bi = li[0], bj = 0;
            #pragma unroll
            for(int j=1;j<16;j++){
                if(lv[j] > bm || (lv[j] == bm && li[j] < bi)){ bm = lv[j]; bi = li[j]; bj = j; }
            }
            float gm = bm; int gi = bi;
            #pragma unroll
            for(int off=16; off; off>>=1){
                float om = __shfl_xor_sync(0xffffffffu, gm, off);
                int   oi = __shfl_xor_sync(0xffffffffu, gi, off);
                if(om > gm || (om == gm && oi < gi)){ gm = om; gi = oi; }
            }
            if(gm == bm && gi == bi){
                lv[bj] = -FLT_MAX; li[bj] = 0x7fffffff;
            }
            if(lane == 0){ stp[it] = gi; g_topk[row*SPARS + it] = gi; }
        }
    }
    __syncthreads();

    if(tid < VDIM){
        float s = 0.f;
        for(int j=0; j<SPARS; j++) s += memv[(size_t)stp[j]*VDIM + tid];
        out[(size_t)row*VDIM + tid] = s;
        g_delta[row*VDIM + tid] = (targets[(size_t)row*VDIM + tid] - s) * (0.1f/32.0f);
    }
}

// ============================================================
__global__ void k_copy(const float* __restrict__ memv, float* __restrict__ out){
    int i = blockIdx.x*blockDim.x + threadIdx.x;
    ((float4*)out)[B_ROWS*VDIM/4 + i] = ((const float4*)memv)[i];
}

__global__ void k_scatter(float* __restrict__ out){
    int g = blockIdx.x*blockDim.x + threadIdx.x;
    int b = g >> 5;
    int idx = g_topk[g];
    float* dst = out + (size_t)(B_ROWS + idx)*VDIM;
    const float* d = &g_delta[b*VDIM];
    #pragma unroll
    for(int vv=0; vv<VDIM; vv++) atomicAdd(dst+vv, d[vv]);
}

// ============================================================
extern "C" void kernel_launch(void* const* d_in, const int* in_sizes, int n_in,
                              void* d_out, int out_size){
    const float* keys    = (const float*)d_in[0];
    const float* targets = (const float*)d_in[1];
    const float* proj    = (const float*)d_in[2];
    const float* memv    = (const float*)d_in[3];
    float* out = (float*)d_out;

    cudaFuncSetAttribute(k_scores, cudaFuncAttributeMaxDynamicSharedMemorySize, SMEM_TOTAL);

    // k_scores at launch position 4 (where ncu capture lands)
    k_cvt   <<<(NK4+NP4)/TPB, TPB>>>(keys, proj);
    k_copy  <<<(MEM*VDIM/4)/TPB, TPB>>>(memv, out);
    k_thr   <<<(B_ROWS*32)/TPB, TPB>>>(keys);
    k_scores<<<dim3(B_ROWS/BM, SPLITS), TPB, SMEM_TOTAL>>>();
    k_merge <<<B_ROWS, TPB>>>(keys, proj, targets, memv, out);
    k_scatter<<<(B_ROWS*SPARS)/TPB, TPB>>>(out);
}